// round 10
// baseline (speedup 1.0000x reference)
#include <cuda_runtime.h>
#include <cuda_fp16.h>
#include <stdint.h>

#define B_ 128
#define T_ 256
#define H_ 512
#define G4 2048          // 4*H, gate-interleaved columns p = 4*jh + gate
#define KW 1024          // weight split-K: [hi(512) | lo(512)]
#define M_ (B_*T_)       // 32768

// ---------------- device scratch (no allocs allowed) ----------------
__device__ __half g_wsplit[4][G4][KW];    // W1,U1,W2,U2: [p][ hi | lo ], fp16
__device__ float  g_bias[2][G4];
__device__ __half g_x[M_][H_];            // single-fp16 activations (big-GEMM A)
__device__ float  g_Zx[M_][G4];           // x@W + b, gate-interleaved
__device__ __half g_h16[B_][H_];          // single global h buffer (write->barrier->read)
__device__ float  g_c[B_][H_];
__device__ unsigned g_flags[2][64];       // per-CTA barrier slots (monotonic, replay-safe)

// ---------------- helpers ----------------
#define MMA16816(d, a, b) asm volatile( \
  "mma.sync.aligned.m16n8k16.row.col.f32.f16.f16.f32 " \
  "{%0,%1,%2,%3}, {%4,%5,%6,%7}, {%8,%9}, {%0,%1,%2,%3};\n" \
  : "+f"(d[0]), "+f"(d[1]), "+f"(d[2]), "+f"(d[3]) \
  : "r"(a[0]), "r"(a[1]), "r"(a[2]), "r"(a[3]), "r"(b[0]), "r"(b[1]))

__device__ __forceinline__ uint32_t s2u(const void* p) {
  return (uint32_t)__cvta_generic_to_shared(p);
}
__device__ __forceinline__ void ldsm4(uint32_t r[4], uint32_t addr) {
  asm volatile("ldmatrix.sync.aligned.m8n8.x4.shared.b16 {%0,%1,%2,%3}, [%4];\n"
    : "=r"(r[0]), "=r"(r[1]), "=r"(r[2]), "=r"(r[3]) : "r"(addr));
}
__device__ __forceinline__ void cpa16(void* s, const void* g) {
  uint32_t sa = s2u(s);
  asm volatile("cp.async.cg.shared.global [%0], [%1], 16;\n" :: "r"(sa), "l"(g));
}
#define CP_COMMIT asm volatile("cp.async.commit_group;\n")
#define CP_WAIT0  asm volatile("cp.async.wait_group 0;\n")

__device__ __forceinline__ float sigf(float x)     { return 1.f / (1.f + __expf(-x)); }
__device__ __forceinline__ float tanhfast(float x) { return 1.f - 2.f / (1.f + __expf(2.f*x)); }

// ---------------- prep (fused, launch #1) ----------------
__global__ void k_prep(const float* __restrict__ W1, const float* __restrict__ U1,
                       const float* __restrict__ W2, const float* __restrict__ U2,
                       const float* __restrict__ b1, const float* __restrict__ b2) {
  int idx = blockIdx.x * blockDim.x + threadIdx.x;
  if (idx < 4 * G4 * 512) {
    int w   = idx >> 20;
    int rem = idx & ((1 << 20) - 1);
    int p   = rem >> 9;
    int k   = rem & 511;
    int jh = p >> 2, gate = p & 3;
    int j = gate * H_ + jh;
    const float* Mt = (w==0) ? W1 : (w==1) ? U1 : (w==2) ? W2 : U2;
    float v = Mt[(size_t)k * G4 + j];
    __half hi = __float2half(v);
    __half lo = __float2half(v - __half2float(hi));
    g_wsplit[w][p][k]       = hi;
    g_wsplit[w][p][512 + k] = lo;
  }
  if (idx < 2 * G4) {
    int l = idx >> 11;
    int p = idx & (G4 - 1);
    int jh = p >> 2, gate = p & 3;
    const float* b = l ? b2 : b1;
    g_bias[l][p] = b[gate * H_ + jh];
  }
  if (idx < B_ * H_) {
    ((__half*)g_h16)[idx] = __float2half(0.f);
    ((float*)g_c)[idx] = 0.f;
  }
}

// ---------------- conv (launch #2): x fp32 -> single fp16 ----------------
__global__ void k_conv(const float* __restrict__ x) {
  int i = blockIdx.x * blockDim.x + threadIdx.x;
  ((__half*)g_x)[i] = __float2half(x[i]);
}

// ---------------- big GEMM: Zx = A(fp16) @ [Whi|Wlo]^T + bias ----------------
struct BigS {
  alignas(16) __half a[2][128][72];
  alignas(16) __half w_hi[2][128][72];
  alignas(16) __half w_lo[2][128][72];
};

__global__ void __launch_bounds__(256, 1) k_gemm_big(int widx, int lidx) {
  extern __shared__ char smraw[];
  BigS& s = *(BigS*)smraw;
  const int tid = threadIdx.x, wid = tid >> 5, lane = tid & 31;
  const int grp = lane >> 2, qid = lane & 3;
  const int mBase = blockIdx.y * 128, nBase = blockIdx.x * 128;
  const int m_off = (wid & 3) * 32, n_off = (wid >> 2) * 64;
  const int aR = lane & 15,                  aC = (lane >> 4) << 3;
  const int bR = ((lane>>4)<<3) + (lane&7),  bC = ((lane >> 3) & 1) << 3;

  float acc[2][8][4];
  #pragma unroll
  for (int mt=0; mt<2; mt++)
    #pragma unroll
    for (int nt=0; nt<8; nt++)
      #pragma unroll
      for (int q=0; q<4; q++) acc[mt][nt][q] = 0.f;

  auto load_blk = [&](int kb, int bufi) {
    int k0 = kb * 64;
    #pragma unroll
    for (int i = tid; i < 1024; i += 256) {
      int r = i >> 3, ch = (i & 7) * 8;
      cpa16(&s.a[bufi][r][ch], &g_x[mBase + r][k0 + ch]);
    }
    #pragma unroll
    for (int i = tid; i < 2048; i += 256) {
      int j = i & 1023;
      int r = j >> 3, ch = (j & 7) * 8;
      if (i < 1024) cpa16(&s.w_hi[bufi][r][ch], &g_wsplit[widx][nBase + r][k0 + ch]);
      else          cpa16(&s.w_lo[bufi][r][ch], &g_wsplit[widx][nBase + r][512 + k0 + ch]);
    }
  };

  uint32_t sa[2], swH[2], swL[2];
  #pragma unroll
  for (int b = 0; b < 2; b++) {
    sa[b]  = s2u(&s.a[b][0][0]);
    swH[b] = s2u(&s.w_hi[b][0][0]);
    swL[b] = s2u(&s.w_lo[b][0][0]);
  }

  load_blk(0, 0); CP_COMMIT;
  for (int kb = 0; kb < 8; kb++) {
    CP_WAIT0; __syncthreads();
    if (kb < 7) { load_blk(kb + 1, (kb + 1) & 1); CP_COMMIT; }
    int bf = kb & 1;
    #pragma unroll
    for (int ks = 0; ks < 4; ks++) {
      const int kk = ks * 16;
      uint32_t af[2][4], wh[4][4], wl[4][4];
      #pragma unroll
      for (int mt = 0; mt < 2; mt++) {
        uint32_t off = (uint32_t)(((m_off + mt*16 + aR) * 72 + kk + aC) * 2);
        ldsm4(af[mt], sa[bf] + off);
      }
      #pragma unroll
      for (int np = 0; np < 4; np++) {
        uint32_t off = (uint32_t)(((n_off + np*16 + bR) * 72 + kk + bC) * 2);
        ldsm4(wh[np], swH[bf] + off);
        ldsm4(wl[np], swL[bf] + off);
      }
      #pragma unroll
      for (int np = 0; np < 4; np++)
        #pragma unroll
        for (int hf = 0; hf < 2; hf++)
          #pragma unroll
          for (int mt = 0; mt < 2; mt++)
            MMA16816(acc[mt][np*2+hf], af[mt], (&wh[np][hf*2]));
      #pragma unroll
      for (int np = 0; np < 4; np++)
        #pragma unroll
        for (int hf = 0; hf < 2; hf++)
          #pragma unroll
          for (int mt = 0; mt < 2; mt++)
            MMA16816(acc[mt][np*2+hf], af[mt], (&wl[np][hf*2]));
    }
    __syncthreads();
  }

  #pragma unroll
  for (int mt = 0; mt < 2; mt++) {
    #pragma unroll
    for (int nt = 0; nt < 8; nt++) {
      int r = mBase + m_off + mt*16 + grp;
      int c = nBase + n_off + nt*8 + qid*2;
      float bx = g_bias[lidx][c], by = g_bias[lidx][c + 1];
      float2 v0 = make_float2(acc[mt][nt][0] + bx, acc[mt][nt][1] + by);
      *(float2*)&g_Zx[r][c] = v0;
      float2 v1 = make_float2(acc[mt][nt][2] + bx, acc[mt][nt][3] + by);
      *(float2*)&g_Zx[r + 8][c] = v1;
    }
  }
}

// ---------------- persistent recurrent pass kernel ----------------
struct StepS {
  alignas(16) __half w_hi[32][520];     // U hi slab, resident per pass
  alignas(16) __half w_lo[32][520];     // U lo slab
  alignas(16) __half a[64][520];        // full-K fp16 h tile (single buffer)
  alignas(16) float zs[64][36];
  alignas(16) float cst[64][8];
  unsigned base;
};

__global__ void __launch_bounds__(256, 1) k_step(int uidx, int writeX, int finalPass,
                                                 float* __restrict__ out) {
  extern __shared__ char smraw[];
  StepS& s = *(StepS*)smraw;
  const int tid = threadIdx.x, wid = tid >> 5, lane = tid & 31;
  const int grp = lane >> 2, qid = lane & 3;
  const int bx = blockIdx.x, by = blockIdx.y;
  const int nBase = bx * 32, mBase = by * 64, jhBase = bx * 8;
  const int m_off = (wid & 3) * 16, n_off = (wid >> 2) * 16;
  const int aR = lane & 15,                  aC = (lane >> 4) << 3;
  const int bR = ((lane>>4)<<3) + (lane&7),  bC = ((lane >> 3) & 1) << 3;

  if (tid == 0) {
    unsigned b;
    asm volatile("ld.acquire.gpu.global.u32 %0, [%1];\n"
                 : "=r"(b) : "l"(&g_flags[by][bx]) : "memory");
    s.base = b;
  }
  // U slab (once per pass): 32 rows x 1024 (hi|lo)
  for (int i = tid; i < 4096; i += 256) {
    int r = i >> 7, ch = (i & 127) * 8;
    uint4 v = *(const uint4*)&g_wsplit[uidx][nBase + r][ch];
    if (ch < 512) *(uint4*)&s.w_hi[r][ch] = v;
    else          *(uint4*)&s.w_lo[r][ch - 512] = v;
  }
  for (int i = tid; i < 512; i += 256)
    s.cst[i >> 3][i & 7] = g_c[mBase + (i >> 3)][jhBase + (i & 7)];

  // prologue: async-load h(0)
  #pragma unroll 4
  for (int i = tid; i < 4096; i += 256) {
    int r = i >> 6, ch = (i & 63) * 8;
    cpa16(&s.a[r][ch], &g_h16[mBase + r][ch]);
  }
  CP_COMMIT;
  __syncthreads();
  const unsigned base = s.base;

  const uint32_t saA = s2u(&s.a[0][0]);
  const uint32_t swH = s2u(&s.w_hi[0][0]), swL = s2u(&s.w_lo[0][0]);
  const uint32_t aOff = (uint32_t)(((m_off + aR) * 520 + aC) * 2);
  const uint32_t wOff = (uint32_t)(((n_off + bR) * 520 + bC) * 2);

  const int b_l = tid >> 2, jh0 = (tid & 3) * 2;   // 2 cells per thread

  for (int t = 0; t < T_; t++) {
    // Zx prefetch (DRAM long-scoreboard overlaps h transfer + mma)
    const float* zrow = &g_Zx[(mBase + b_l) * T_ + t][nBase + jh0 * 4];
    float4 zx0 = *(const float4*)zrow;
    float4 zx1 = *(const float4*)(zrow + 4);

    CP_WAIT0;            // h(t) smem transfer complete (this thread's chunks)
    __syncthreads();     // all threads' chunks visible

    float acc[2][4];
    #pragma unroll
    for (int nt=0; nt<2; nt++)
      #pragma unroll
      for (int q=0; q<4; q++) acc[nt][q] = 0.f;

    #pragma unroll 8
    for (int ks = 0; ks < 32; ks++) {
      uint32_t af[4], wh[4], wl[4];
      ldsm4(af, saA + aOff + ks * 32);
      ldsm4(wh, swH + wOff + ks * 32);
      ldsm4(wl, swL + wOff + ks * 32);
      #pragma unroll
      for (int hf = 0; hf < 2; hf++) MMA16816(acc[hf], af, (&wh[hf*2]));
      #pragma unroll
      for (int hf = 0; hf < 2; hf++) MMA16816(acc[hf], af, (&wl[hf*2]));
    }

    // accumulators -> smem
    #pragma unroll
    for (int nt = 0; nt < 2; nt++) {
      int c = n_off + nt*8 + qid*2;
      s.zs[m_off + grp][c]         = acc[nt][0];
      s.zs[m_off + grp][c + 1]     = acc[nt][1];
      s.zs[m_off + 8 + grp][c]     = acc[nt][2];
      s.zs[m_off + 8 + grp][c + 1] = acc[nt][3];
    }
    __syncthreads();     // sync1: zs visible (also: all mma reads of s.a done)

    // gates + state update: 2 cells per thread
    float hv[2];
    #pragma unroll
    for (int q = 0; q < 2; q++) {
      int jh = jh0 + q;
      float4 z4 = q ? zx1 : zx0;
      float zi = s.zs[b_l][jh*4 + 0] + z4.x;
      float zf = s.zs[b_l][jh*4 + 1] + z4.y;
      float zg = s.zs[b_l][jh*4 + 2] + z4.z;
      float zo = s.zs[b_l][jh*4 + 3] + z4.w;
      float ig = sigf(zi), fg = sigf(zf), gg = tanhfast(zg), og = sigf(zo);
      float c0 = s.cst[b_l][jh];
      float cn = fg * c0 + ig * gg;
      s.cst[b_l][jh] = cn;
      hv[q] = og * tanhfast(cn);
    }
    {
      int bg = mBase + b_l, jg = jhBase + jh0;
      __half2 ph;
      ph.x = __float2half(hv[0]);
      ph.y = __float2half(hv[1]);
      *(__half2*)&g_h16[bg][jg] = ph;
      if (writeX) {
        int m = bg * T_ + t;
        *(__half2*)&g_x[m][jg] = ph;
      }
      if (finalPass && t == T_ - 1) {
        out[bg * H_ + jg]     = hv[0];
        out[bg * H_ + jg + 1] = hv[1];
      }
    }

    if (t < T_ - 1) {
      __syncthreads();   // sync2: all h stores issued
      unsigned target = base + (unsigned)t + 1;
      if (tid == 0) {
        asm volatile("fence.acq_rel.gpu;\n" ::: "memory");
        asm volatile("st.release.gpu.global.u32 [%0], %1;\n"
                     :: "l"(&g_flags[by][bx]), "r"(target) : "memory");
      }
      if (tid < 64) {
        unsigned v;
        asm volatile("ld.acquire.gpu.global.u32 %0, [%1];\n"
                     : "=r"(v) : "l"(&g_flags[by][tid]) : "memory");
        while (v < target) {
          __nanosleep(64);
          asm volatile("ld.acquire.gpu.global.u32 %0, [%1];\n"
                       : "=r"(v) : "l"(&g_flags[by][tid]) : "memory");
        }
      }
      __syncthreads();   // sync3: barrier passed for whole CTA

      // issue h(t+1) load (overlaps next iteration's Zx LDG)
      #pragma unroll 4
      for (int i = tid; i < 4096; i += 256) {
        int r = i >> 6, ch = (i & 63) * 8;
        cpa16(&s.a[r][ch], &g_h16[mBase + r][ch]);
      }
      CP_COMMIT;
    }
  }

  __syncthreads();
  for (int i = tid; i < 512; i += 256)
    g_c[mBase + (i >> 3)][jhBase + (i & 7)] = s.cst[i >> 3][i & 7];
}

// ---------------- launch ----------------
extern "C" void kernel_launch(void* const* d_in, const int* in_sizes, int n_in,
                              void* d_out, int out_size) {
  const float* x  = (const float*)d_in[0];
  const float* W1 = (const float*)d_in[1];
  const float* U1 = (const float*)d_in[2];
  const float* b1 = (const float*)d_in[3];
  const float* W2 = (const float*)d_in[4];
  const float* U2 = (const float*)d_in[5];
  const float* b2 = (const float*)d_in[6];

  cudaFuncSetAttribute(k_gemm_big, cudaFuncAttributeMaxDynamicSharedMemorySize, (int)sizeof(BigS));
  cudaFuncSetAttribute(k_step,     cudaFuncAttributeMaxDynamicSharedMemorySize, (int)sizeof(StepS));

  k_prep<<<(4 * G4 * 512 + 255) / 256, 256>>>(W1, U1, W2, U2, b1, b2);
  k_conv<<<(M_ * H_ + 255) / 256, 256>>>(x);

  for (int pass = 0; pass < 6; ++pass) {
    int widx = (pass < 5) ? 0 : 2;
    int uidx = widx + 1;
    int lidx = (pass < 5) ? 0 : 1;
    k_gemm_big<<<dim3(G4 / 128, M_ / 128), 256, sizeof(BigS)>>>(widx, lidx);
    k_step<<<dim3(64, 2), 256, sizeof(StepS)>>>(uidx, (pass < 5) ? 1 : 0,
                                                (pass == 5) ? 1 : 0, (float*)d_out);
  }
}

// round 11
// speedup vs baseline: 1.6958x; 1.6958x over previous
#include <cuda_runtime.h>
#include <cuda_fp16.h>
#include <stdint.h>

#define B_ 128
#define T_ 256
#define H_ 512
#define G4 2048          // 4*H, gate-interleaved columns p = 4*jh + gate
#define M_ (B_*T_)       // 32768

// ---------------- device scratch (no allocs allowed) ----------------
__device__ __half g_w16[4][G4][512];      // W1,U1,W2,U2 fp16, transposed [p][k]
__device__ float  g_bias[2][G4];
__device__ __half g_x[M_][H_];            // fp16 activations (big-GEMM A), m = b*T+t
__device__ float  g_Zx[M_][G4];           // x@W + b, gate-interleaved
__device__ __half g_hT[64][B_][8];        // h transposed: [jh_group][batch][8 jh]
__device__ float  g_c[B_][H_];
__device__ unsigned g_flags[2][64][32];   // per-CTA barrier flag, 1 per 128B line

// ---------------- helpers ----------------
#define MMA16816(d, a, b) asm volatile( \
  "mma.sync.aligned.m16n8k16.row.col.f32.f16.f16.f32 " \
  "{%0,%1,%2,%3}, {%4,%5,%6,%7}, {%8,%9}, {%0,%1,%2,%3};\n" \
  : "+f"(d[0]), "+f"(d[1]), "+f"(d[2]), "+f"(d[3]) \
  : "r"(a[0]), "r"(a[1]), "r"(a[2]), "r"(a[3]), "r"(b[0]), "r"(b[1]))

__device__ __forceinline__ uint32_t s2u(const void* p) {
  return (uint32_t)__cvta_generic_to_shared(p);
}
__device__ __forceinline__ void ldsm4(uint32_t r[4], uint32_t addr) {
  asm volatile("ldmatrix.sync.aligned.m8n8.x4.shared.b16 {%0,%1,%2,%3}, [%4];\n"
    : "=r"(r[0]), "=r"(r[1]), "=r"(r[2]), "=r"(r[3]) : "r"(addr));
}
__device__ __forceinline__ void cpa16(void* s, const void* g) {
  uint32_t sa = s2u(s);
  asm volatile("cp.async.cg.shared.global [%0], [%1], 16;\n" :: "r"(sa), "l"(g));
}
#define CP_COMMIT asm volatile("cp.async.commit_group;\n")
#define CP_WAIT0  asm volatile("cp.async.wait_group 0;\n")

__device__ __forceinline__ float sigf(float x)     { return 1.f / (1.f + __expf(-x)); }
__device__ __forceinline__ float tanhfast(float x) { return 1.f - 2.f / (1.f + __expf(2.f*x)); }

// ---------------- prep (fused, launch #1) ----------------
__global__ void k_prep(const float* __restrict__ W1, const float* __restrict__ U1,
                       const float* __restrict__ W2, const float* __restrict__ U2,
                       const float* __restrict__ b1, const float* __restrict__ b2) {
  int idx = blockIdx.x * blockDim.x + threadIdx.x;
  if (idx < 4 * G4 * 512) {
    int w   = idx >> 20;
    int rem = idx & ((1 << 20) - 1);
    int p   = rem >> 9;
    int k   = rem & 511;
    int jh = p >> 2, gate = p & 3;
    int j = gate * H_ + jh;
    const float* Mt = (w==0) ? W1 : (w==1) ? U1 : (w==2) ? W2 : U2;
    g_w16[w][p][k] = __float2half(Mt[(size_t)k * G4 + j]);
  }
  if (idx < 2 * G4) {
    int l = idx >> 11;
    int p = idx & (G4 - 1);
    int jh = p >> 2, gate = p & 3;
    const float* b = l ? b2 : b1;
    g_bias[l][p] = b[gate * H_ + jh];
  }
  if (idx < B_ * H_) {
    ((__half*)g_hT)[idx] = __float2half(0.f);
    ((float*)g_c)[idx] = 0.f;
  }
}

// ---------------- conv (launch #2): x fp32 -> fp16 ----------------
__global__ void k_conv(const float* __restrict__ x) {
  int i = blockIdx.x * blockDim.x + threadIdx.x;
  ((__half*)g_x)[i] = __float2half(x[i]);
}

// ---------------- big GEMM: Zx = A(fp16) @ W(fp16)^T + bias ----------------
struct BigS {
  alignas(16) __half a[2][128][72];
  alignas(16) __half w[2][128][72];
};

__global__ void __launch_bounds__(256, 1) k_gemm_big(int widx, int lidx) {
  extern __shared__ char smraw[];
  BigS& s = *(BigS*)smraw;
  const int tid = threadIdx.x, wid = tid >> 5, lane = tid & 31;
  const int grp = lane >> 2, qid = lane & 3;
  const int mBase = blockIdx.y * 128, nBase = blockIdx.x * 128;
  const int m_off = (wid & 3) * 32, n_off = (wid >> 2) * 64;
  const int aR = lane & 15,                  aC = (lane >> 4) << 3;
  const int bR = ((lane>>4)<<3) + (lane&7),  bC = ((lane >> 3) & 1) << 3;

  float acc[2][8][4];
  #pragma unroll
  for (int mt=0; mt<2; mt++)
    #pragma unroll
    for (int nt=0; nt<8; nt++)
      #pragma unroll
      for (int q=0; q<4; q++) acc[mt][nt][q] = 0.f;

  auto load_blk = [&](int kb, int bufi) {
    int k0 = kb * 64;
    #pragma unroll
    for (int i = tid; i < 1024; i += 256) {
      int r = i >> 3, ch = (i & 7) * 8;
      cpa16(&s.a[bufi][r][ch], &g_x[mBase + r][k0 + ch]);
      cpa16(&s.w[bufi][r][ch], &g_w16[widx][nBase + r][k0 + ch]);
    }
  };

  uint32_t sa[2], sw[2];
  #pragma unroll
  for (int b = 0; b < 2; b++) {
    sa[b] = s2u(&s.a[b][0][0]);
    sw[b] = s2u(&s.w[b][0][0]);
  }

  load_blk(0, 0); CP_COMMIT;
  for (int kb = 0; kb < 8; kb++) {
    CP_WAIT0; __syncthreads();
    if (kb < 7) { load_blk(kb + 1, (kb + 1) & 1); CP_COMMIT; }
    int bf = kb & 1;
    #pragma unroll
    for (int ks = 0; ks < 4; ks++) {
      const int kk = ks * 16;
      uint32_t af[2][4], wf[4][4];
      #pragma unroll
      for (int mt = 0; mt < 2; mt++) {
        uint32_t off = (uint32_t)(((m_off + mt*16 + aR) * 72 + kk + aC) * 2);
        ldsm4(af[mt], sa[bf] + off);
      }
      #pragma unroll
      for (int np = 0; np < 4; np++) {
        uint32_t off = (uint32_t)(((n_off + np*16 + bR) * 72 + kk + bC) * 2);
        ldsm4(wf[np], sw[bf] + off);
      }
      #pragma unroll
      for (int np = 0; np < 4; np++)
        #pragma unroll
        for (int hf = 0; hf < 2; hf++)
          #pragma unroll
          for (int mt = 0; mt < 2; mt++)
            MMA16816(acc[mt][np*2+hf], af[mt], (&wf[np][hf*2]));
    }
    __syncthreads();
  }

  #pragma unroll
  for (int mt = 0; mt < 2; mt++) {
    #pragma unroll
    for (int nt = 0; nt < 8; nt++) {
      int r = mBase + m_off + mt*16 + grp;
      int c = nBase + n_off + nt*8 + qid*2;
      float bx = g_bias[lidx][c], by = g_bias[lidx][c + 1];
      float2 v0 = make_float2(acc[mt][nt][0] + bx, acc[mt][nt][1] + by);
      *(float2*)&g_Zx[r][c] = v0;
      float2 v1 = make_float2(acc[mt][nt][2] + bx, acc[mt][nt][3] + by);
      *(float2*)&g_Zx[r + 8][c] = v1;
    }
  }
}

// ---------------- persistent recurrent pass kernel ----------------
struct StepS {
  alignas(16) __half w[32][520];       // U slab (single fp16), resident per pass
  alignas(16) __half a[2][64][264];    // h tile, 2 stages x 256 cols
  alignas(16) float zs[64][36];
  alignas(16) float cst[64][8];
  unsigned base;
};

__global__ void __launch_bounds__(256, 1) k_step(int uidx, int writeX, int finalPass,
                                                 float* __restrict__ out) {
  extern __shared__ char smraw[];
  StepS& s = *(StepS*)smraw;
  const int tid = threadIdx.x, wid = tid >> 5, lane = tid & 31;
  const int grp = lane >> 2, qid = lane & 3;
  const int bx = blockIdx.x, by = blockIdx.y;
  const int nBase = bx * 32, mBase = by * 64;
  const int m_off = (wid & 3) * 16, n_off = (wid >> 2) * 16;
  const int aR = lane & 15,                  aC = (lane >> 4) << 3;
  const int bR = ((lane>>4)<<3) + (lane&7),  bC = ((lane >> 3) & 1) << 3;

  if (tid == 0) {
    unsigned b;
    asm volatile("ld.acquire.gpu.global.u32 %0, [%1];\n"
                 : "=r"(b) : "l"(&g_flags[by][bx][0]) : "memory");
    s.base = b;
  }
  // U slab (once per pass): 32 rows x 512
  for (int i = tid; i < 2048; i += 256) {
    int r = i >> 6, ch = (i & 63) * 8;
    *(uint4*)&s.w[r][ch] = *(const uint4*)&g_w16[uidx][nBase + r][ch];
  }
  for (int i = tid; i < 512; i += 256)
    s.cst[i >> 3][i & 7] = g_c[mBase + (i >> 3)][(bx * 8) + (i & 7)];

  // stage loader: stage st covers h groups [st*32, st*32+32)
  auto load_a = [&](int st, int bufi) {
    #pragma unroll
    for (int i = tid; i < 2048; i += 256) {
      int r = i >> 5, gg = i & 31;
      cpa16(&s.a[bufi][r][gg * 8], &g_hT[st * 32 + gg][mBase + r][0]);
    }
  };

  // prologue: stage 0 of h(0)
  load_a(0, 0); CP_COMMIT;
  __syncthreads();
  const unsigned base = s.base;

  uint32_t sa[2];
  sa[0] = s2u(&s.a[0][0][0]); sa[1] = s2u(&s.a[1][0][0]);
  const uint32_t swW = s2u(&s.w[0][0]);
  const uint32_t aOff = (uint32_t)(((m_off + aR) * 264 + aC) * 2);
  const uint32_t wOff = (uint32_t)(((n_off + bR) * 520 + bC) * 2);

  const int b_l = tid >> 2, jh0 = (tid & 3) * 2;   // 2 cells per thread

  for (int t = 0; t < T_; t++) {
    // Zx prefetch (DRAM long-scoreboard overlaps h transfer + mma)
    const float* zrow = &g_Zx[(mBase + b_l) * T_ + t][nBase + jh0 * 4];
    float4 zx0 = *(const float4*)zrow;
    float4 zx1 = *(const float4*)(zrow + 4);

    float acc[2][4];
    #pragma unroll
    for (int nt=0; nt<2; nt++)
      #pragma unroll
      for (int q=0; q<4; q++) acc[nt][q] = 0.f;

    #pragma unroll
    for (int kb = 0; kb < 2; kb++) {
      CP_WAIT0; __syncthreads();
      if (kb == 0) { load_a(1, 1); CP_COMMIT; }
      int bf = kb;
      #pragma unroll
      for (int ks = 0; ks < 16; ks++) {
        const int kw = kb * 256 + ks * 16;
        uint32_t af[4], wf[4];
        ldsm4(af, sa[bf] + aOff + ks * 32);
        ldsm4(wf, swW + wOff + kw * 2);
        #pragma unroll
        for (int hf = 0; hf < 2; hf++) MMA16816(acc[hf], af, (&wf[hf*2]));
      }
      if (kb == 0) __syncthreads();
    }

    // accumulators -> smem
    #pragma unroll
    for (int nt = 0; nt < 2; nt++) {
      int c = n_off + nt*8 + qid*2;
      s.zs[m_off + grp][c]         = acc[nt][0];
      s.zs[m_off + grp][c + 1]     = acc[nt][1];
      s.zs[m_off + 8 + grp][c]     = acc[nt][2];
      s.zs[m_off + 8 + grp][c + 1] = acc[nt][3];
    }
    __syncthreads();     // sync: zs visible; all mma reads of s.a done

    // gates + state update: 2 cells per thread
    float hv[2];
    #pragma unroll
    for (int q = 0; q < 2; q++) {
      int jh = jh0 + q;
      float4 z4 = q ? zx1 : zx0;
      float zi = s.zs[b_l][jh*4 + 0] + z4.x;
      float zf = s.zs[b_l][jh*4 + 1] + z4.y;
      float zg = s.zs[b_l][jh*4 + 2] + z4.z;
      float zo = s.zs[b_l][jh*4 + 3] + z4.w;
      float ig = sigf(zi), fg = sigf(zf), gg = tanhfast(zg), og = sigf(zo);
      float c0 = s.cst[b_l][jh];
      float cn = fg * c0 + ig * gg;
      s.cst[b_l][jh] = cn;
      hv[q] = og * tanhfast(cn);
    }
    {
      int bg = mBase + b_l;
      __half2 ph;
      ph.x = __float2half(hv[0]);
      ph.y = __float2half(hv[1]);
      *(__half2*)&g_hT[bx][bg][jh0] = ph;          // CTA-exclusive cache lines
      if (writeX) {
        int m = bg * T_ + t;
        *(__half2*)&g_x[m][bx * 8 + jh0] = ph;
      }
      if (finalPass && t == T_ - 1) {
        out[bg * H_ + bx * 8 + jh0]     = hv[0];
        out[bg * H_ + bx * 8 + jh0 + 1] = hv[1];
      }
    }

    if (t < T_ - 1) {
      __syncthreads();   // all h stores issued
      unsigned target = base + (unsigned)t + 1;
      if (tid == 0) {
        asm volatile("fence.acq_rel.gpu;\n" ::: "memory");
        asm volatile("st.release.gpu.global.u32 [%0], %1;\n"
                     :: "l"(&g_flags[by][bx][0]), "r"(target) : "memory");
      }
      if (tid < 64) {
        unsigned v;
        do {
          asm volatile("ld.acquire.gpu.global.u32 %0, [%1];\n"
                       : "=r"(v) : "l"(&g_flags[by][tid][0]) : "memory");
        } while (v < target);
      }
      __syncthreads();   // barrier passed for whole CTA

      // issue stage 0 of h(t+1)
      load_a(0, 0); CP_COMMIT;
    }
  }

  __syncthreads();
  for (int i = tid; i < 512; i += 256)
    g_c[mBase + (i >> 3)][(bx * 8) + (i & 7)] = s.cst[i >> 3][i & 7];
}

// ---------------- launch ----------------
extern "C" void kernel_launch(void* const* d_in, const int* in_sizes, int n_in,
                              void* d_out, int out_size) {
  const float* x  = (const float*)d_in[0];
  const float* W1 = (const float*)d_in[1];
  const float* U1 = (const float*)d_in[2];
  const float* b1 = (const float*)d_in[3];
  const float* W2 = (const float*)d_in[4];
  const float* U2 = (const float*)d_in[5];
  const float* b2 = (const float*)d_in[6];

  cudaFuncSetAttribute(k_gemm_big, cudaFuncAttributeMaxDynamicSharedMemorySize, (int)sizeof(BigS));
  cudaFuncSetAttribute(k_step,     cudaFuncAttributeMaxDynamicSharedMemorySize, (int)sizeof(StepS));

  k_prep<<<(4 * G4 * 512 + 255) / 256, 256>>>(W1, U1, W2, U2, b1, b2);
  k_conv<<<(M_ * H_ + 255) / 256, 256>>>(x);

  for (int pass = 0; pass < 6; ++pass) {
    int widx = (pass < 5) ? 0 : 2;
    int uidx = widx + 1;
    int lidx = (pass < 5) ? 0 : 1;
    k_gemm_big<<<dim3(G4 / 128, M_ / 128), 256, sizeof(BigS)>>>(widx, lidx);
    k_step<<<dim3(64, 2), 256, sizeof(StepS)>>>(uidx, (pass < 5) ? 1 : 0,
                                                (pass == 5) ? 1 : 0, (float*)d_out);
  }
}

// round 12
// speedup vs baseline: 2.5424x; 1.4993x over previous
#include <cuda_runtime.h>
#include <cuda_fp16.h>
#include <stdint.h>

#define B_ 128
#define T_ 256
#define H_ 512
#define G4 2048          // 4*H, gate-interleaved columns p = 4*jh + gate
#define M_ (B_*T_)       // 32768

// ---------------- device scratch (no allocs allowed) ----------------
__device__ __half g_w16[4][G4][512];      // W1,U1,W2,U2 fp16, transposed [p][k]
__device__ float  g_bias[2][G4];
__device__ __half g_x[M_][H_];            // fp16 activations (big-GEMM A), m = b*T+t
__device__ float  g_Zx[M_][G4];           // x@W + b, gate-interleaved
__device__ __half g_hT[64][B_][8];        // h transposed: [jh_group][batch][8 jh]
__device__ float  g_c[B_][H_];
__device__ unsigned g_flags[4][32][32];   // [m-group][cta][pad]: 1 flag per 128B line

// ---------------- helpers ----------------
#define MMA16816(d, a, b) asm volatile( \
  "mma.sync.aligned.m16n8k16.row.col.f32.f16.f16.f32 " \
  "{%0,%1,%2,%3}, {%4,%5,%6,%7}, {%8,%9}, {%0,%1,%2,%3};\n" \
  : "+f"(d[0]), "+f"(d[1]), "+f"(d[2]), "+f"(d[3]) \
  : "r"(a[0]), "r"(a[1]), "r"(a[2]), "r"(a[3]), "r"(b[0]), "r"(b[1]))

__device__ __forceinline__ uint32_t s2u(const void* p) {
  return (uint32_t)__cvta_generic_to_shared(p);
}
__device__ __forceinline__ void ldsm4(uint32_t r[4], uint32_t addr) {
  asm volatile("ldmatrix.sync.aligned.m8n8.x4.shared.b16 {%0,%1,%2,%3}, [%4];\n"
    : "=r"(r[0]), "=r"(r[1]), "=r"(r[2]), "=r"(r[3]) : "r"(addr));
}
__device__ __forceinline__ void cpa16(void* s, const void* g) {
  uint32_t sa = s2u(s);
  asm volatile("cp.async.cg.shared.global [%0], [%1], 16;\n" :: "r"(sa), "l"(g));
}
#define CP_COMMIT asm volatile("cp.async.commit_group;\n")
#define CP_WAIT0  asm volatile("cp.async.wait_group 0;\n")
#define CP_WAIT1  asm volatile("cp.async.wait_group 1;\n")

__device__ __forceinline__ float sigf(float x)     { return 1.f / (1.f + __expf(-x)); }
__device__ __forceinline__ float tanhfast(float x) { return 1.f - 2.f / (1.f + __expf(2.f*x)); }

// ---------------- prep (fused, launch #1) ----------------
__global__ void k_prep(const float* __restrict__ W1, const float* __restrict__ U1,
                       const float* __restrict__ W2, const float* __restrict__ U2,
                       const float* __restrict__ b1, const float* __restrict__ b2) {
  int idx = blockIdx.x * blockDim.x + threadIdx.x;
  if (idx < 4 * G4 * 512) {
    int w   = idx >> 20;
    int rem = idx & ((1 << 20) - 1);
    int p   = rem >> 9;
    int k   = rem & 511;
    int jh = p >> 2, gate = p & 3;
    int j = gate * H_ + jh;
    const float* Mt = (w==0) ? W1 : (w==1) ? U1 : (w==2) ? W2 : U2;
    g_w16[w][p][k] = __float2half(Mt[(size_t)k * G4 + j]);
  }
  if (idx < 2 * G4) {
    int l = idx >> 11;
    int p = idx & (G4 - 1);
    int jh = p >> 2, gate = p & 3;
    const float* b = l ? b2 : b1;
    g_bias[l][p] = b[gate * H_ + jh];
  }
  if (idx < B_ * H_) {
    ((__half*)g_hT)[idx] = __float2half(0.f);
    ((float*)g_c)[idx] = 0.f;
  }
}

// ---------------- conv (launch #2): x fp32 -> fp16 ----------------
__global__ void k_conv(const float* __restrict__ x) {
  int i = blockIdx.x * blockDim.x + threadIdx.x;
  ((__half*)g_x)[i] = __float2half(x[i]);
}

// ---------------- big GEMM: Zx = A(fp16) @ W(fp16)^T + bias ----------------
struct BigS {
  alignas(16) __half a[2][128][72];
  alignas(16) __half w[2][128][72];
};

__global__ void __launch_bounds__(256, 1) k_gemm_big(int widx, int lidx) {
  extern __shared__ char smraw[];
  BigS& s = *(BigS*)smraw;
  const int tid = threadIdx.x, wid = tid >> 5, lane = tid & 31;
  const int grp = lane >> 2, qid = lane & 3;
  const int mBase = blockIdx.y * 128, nBase = blockIdx.x * 128;
  const int m_off = (wid & 3) * 32, n_off = (wid >> 2) * 64;
  const int aR = lane & 15,                  aC = (lane >> 4) << 3;
  const int bR = ((lane>>4)<<3) + (lane&7),  bC = ((lane >> 3) & 1) << 3;

  float acc[2][8][4];
  #pragma unroll
  for (int mt=0; mt<2; mt++)
    #pragma unroll
    for (int nt=0; nt<8; nt++)
      #pragma unroll
      for (int q=0; q<4; q++) acc[mt][nt][q] = 0.f;

  auto load_blk = [&](int kb, int bufi) {
    int k0 = kb * 64;
    #pragma unroll
    for (int i = tid; i < 1024; i += 256) {
      int r = i >> 3, ch = (i & 7) * 8;
      cpa16(&s.a[bufi][r][ch], &g_x[mBase + r][k0 + ch]);
      cpa16(&s.w[bufi][r][ch], &g_w16[widx][nBase + r][k0 + ch]);
    }
  };

  uint32_t sa[2], sw[2];
  #pragma unroll
  for (int b = 0; b < 2; b++) {
    sa[b] = s2u(&s.a[b][0][0]);
    sw[b] = s2u(&s.w[b][0][0]);
  }

  load_blk(0, 0); CP_COMMIT;
  for (int kb = 0; kb < 8; kb++) {
    CP_WAIT0; __syncthreads();
    if (kb < 7) { load_blk(kb + 1, (kb + 1) & 1); CP_COMMIT; }
    int bf = kb & 1;
    #pragma unroll
    for (int ks = 0; ks < 4; ks++) {
      const int kk = ks * 16;
      uint32_t af[2][4], wf[4][4];
      #pragma unroll
      for (int mt = 0; mt < 2; mt++) {
        uint32_t off = (uint32_t)(((m_off + mt*16 + aR) * 72 + kk + aC) * 2);
        ldsm4(af[mt], sa[bf] + off);
      }
      #pragma unroll
      for (int np = 0; np < 4; np++) {
        uint32_t off = (uint32_t)(((n_off + np*16 + bR) * 72 + kk + bC) * 2);
        ldsm4(wf[np], sw[bf] + off);
      }
      #pragma unroll
      for (int np = 0; np < 4; np++)
        #pragma unroll
        for (int hf = 0; hf < 2; hf++)
          #pragma unroll
          for (int mt = 0; mt < 2; mt++)
            MMA16816(acc[mt][np*2+hf], af[mt], (&wf[np][hf*2]));
    }
    __syncthreads();
  }

  #pragma unroll
  for (int mt = 0; mt < 2; mt++) {
    #pragma unroll
    for (int nt = 0; nt < 8; nt++) {
      int r = mBase + m_off + mt*16 + grp;
      int c = nBase + n_off + nt*8 + qid*2;
      float bx = g_bias[lidx][c], by = g_bias[lidx][c + 1];
      float2 v0 = make_float2(acc[mt][nt][0] + bx, acc[mt][nt][1] + by);
      *(float2*)&g_Zx[r][c] = v0;
      float2 v1 = make_float2(acc[mt][nt][2] + bx, acc[mt][nt][3] + by);
      *(float2*)&g_Zx[r + 8][c] = v1;
    }
  }
}

// ---------------- persistent recurrent pass kernel ----------------
// Tile: m=32 batch rows x n=64 gate cols (16 jh). Grid (32, 4) = 128 CTAs.
// Barrier groups: per m-group (32 CTAs each), 4 independent groups.
struct StepS {
  alignas(16) __half w[64][520];       // U slab (64 p-cols x 512), resident per pass
  alignas(16) __half a[2][32][264];    // h tile, 2 stages x (32 rows x 256 cols)
  alignas(16) float zs[32][68];
  alignas(16) float cst[32][16];
  unsigned base;
};

__global__ void __launch_bounds__(256, 1) k_step(int uidx, int writeX, int finalPass,
                                                 float* __restrict__ out) {
  extern __shared__ char smraw[];
  StepS& s = *(StepS*)smraw;
  const int tid = threadIdx.x, wid = tid >> 5, lane = tid & 31;
  const int grp = lane >> 2, qid = lane & 3;
  const int bx = blockIdx.x, my = blockIdx.y;
  const int nBase = bx * 64, mBase = my * 32, jhBase = bx * 16;
  const int m_off = (wid & 1) * 16, n_off = (wid >> 1) * 16;
  const int aR = lane & 15,                  aC = (lane >> 4) << 3;
  const int bR = ((lane>>4)<<3) + (lane&7),  bC = ((lane >> 3) & 1) << 3;

  if (tid == 0) {
    unsigned b;
    asm volatile("ld.acquire.gpu.global.u32 %0, [%1];\n"
                 : "=r"(b) : "l"(&g_flags[my][bx][0]) : "memory");
    s.base = b;
  }
  // U slab (once per pass): 64 rows x 512
  for (int i = tid; i < 4096; i += 256) {
    int r = i >> 6, ch = (i & 63) * 8;
    *(uint4*)&s.w[r][ch] = *(const uint4*)&g_w16[uidx][nBase + r][ch];
  }
  // c state: 32 rows x 16 jh
  for (int i = tid; i < 512; i += 256)
    s.cst[i >> 4][i & 15] = g_c[mBase + (i >> 4)][jhBase + (i & 15)];

  // stage loader: stage st covers jh groups [st*32, st*32+32)
  auto load_a = [&](int st, int bufi) {
    #pragma unroll
    for (int i = tid; i < 1024; i += 256) {
      int r = i >> 5, gg = i & 31;
      cpa16(&s.a[bufi][r][gg * 8], &g_hT[st * 32 + gg][mBase + r][0]);
    }
  };

  // prologue: both stages of h(0), split commit groups
  load_a(0, 0); CP_COMMIT;
  load_a(1, 1); CP_COMMIT;
  __syncthreads();
  const unsigned base = s.base;

  uint32_t sa[2];
  sa[0] = s2u(&s.a[0][0][0]); sa[1] = s2u(&s.a[1][0][0]);
  const uint32_t swW = s2u(&s.w[0][0]);
  const uint32_t aOff = (uint32_t)(((m_off + aR) * 264 + aC) * 2);
  const uint32_t wOff = (uint32_t)(((n_off + bR) * 520 + bC) * 2);

  const int b_l = tid >> 3, jh0 = (tid & 7) * 2;   // 2 cells per thread

  for (int t = 0; t < T_; t++) {
    // Zx prefetch (long-scoreboard; consumed after mma)
    const float* zrow = &g_Zx[(mBase + b_l) * T_ + t][nBase + jh0 * 4];
    float4 zx0 = *(const float4*)zrow;
    float4 zx1 = *(const float4*)(zrow + 4);

    float acc[2][4];
    #pragma unroll
    for (int nt=0; nt<2; nt++)
      #pragma unroll
      for (int q=0; q<4; q++) acc[nt][q] = 0.f;

    // stage 0: K cols 0..255
    CP_WAIT1; __syncthreads();
    #pragma unroll
    for (int ks = 0; ks < 16; ks++) {
      uint32_t af[4], wf[4];
      ldsm4(af, sa[0] + aOff + ks * 32);
      ldsm4(wf, swW + wOff + (ks * 16) * 2);
      MMA16816(acc[0], af, (&wf[0]));
      MMA16816(acc[1], af, (&wf[2]));
    }
    // stage 1: K cols 256..511
    CP_WAIT0; __syncthreads();
    #pragma unroll
    for (int ks = 0; ks < 16; ks++) {
      uint32_t af[4], wf[4];
      ldsm4(af, sa[1] + aOff + ks * 32);
      ldsm4(wf, swW + wOff + (256 + ks * 16) * 2);
      MMA16816(acc[0], af, (&wf[0]));
      MMA16816(acc[1], af, (&wf[2]));
    }

    // accumulators -> smem
    #pragma unroll
    for (int nt = 0; nt < 2; nt++) {
      int c = n_off + nt*8 + qid*2;
      s.zs[m_off + grp][c]         = acc[nt][0];
      s.zs[m_off + grp][c + 1]     = acc[nt][1];
      s.zs[m_off + 8 + grp][c]     = acc[nt][2];
      s.zs[m_off + 8 + grp][c + 1] = acc[nt][3];
    }
    __syncthreads();     // zs visible; all mma reads of s.a done

    // gates + state update: 2 cells per thread (b_l, jh0), (b_l, jh0+1)
    float hv[2];
    #pragma unroll
    for (int q = 0; q < 2; q++) {
      int jh = jh0 + q;
      float4 z4 = q ? zx1 : zx0;
      float zi = s.zs[b_l][jh*4 + 0] + z4.x;
      float zf = s.zs[b_l][jh*4 + 1] + z4.y;
      float zg = s.zs[b_l][jh*4 + 2] + z4.z;
      float zo = s.zs[b_l][jh*4 + 3] + z4.w;
      float ig = sigf(zi), fg = sigf(zf), gg = tanhfast(zg), og = sigf(zo);
      float c0 = s.cst[b_l][jh];
      float cn = fg * c0 + ig * gg;
      s.cst[b_l][jh] = cn;
      hv[q] = og * tanhfast(cn);
    }
    {
      int bg = mBase + b_l;
      int jhg = jhBase + jh0;                      // global jh (even)
      __half2 ph;
      ph.x = __float2half(hv[0]);
      ph.y = __float2half(hv[1]);
      *(__half2*)&g_hT[jhg >> 3][bg][jhg & 7] = ph;  // group-exclusive lines per CTA
      if (writeX) {
        int m = bg * T_ + t;
        *(__half2*)&g_x[m][jhg] = ph;
      }
      if (finalPass && t == T_ - 1) {
        out[bg * H_ + jhg]     = hv[0];
        out[bg * H_ + jhg + 1] = hv[1];
      }
    }

    if (t < T_ - 1) {
      __syncthreads();   // all h stores issued
      unsigned target = base + (unsigned)t + 1;
      if (tid == 0) {
        asm volatile("fence.acq_rel.gpu;\n" ::: "memory");
        asm volatile("st.release.gpu.global.u32 [%0], %1;\n"
                     :: "l"(&g_flags[my][bx][0]), "r"(target) : "memory");
      }
      if (tid < 32) {
        unsigned v;
        do {
          asm volatile("ld.acquire.gpu.global.u32 %0, [%1];\n"
                       : "=r"(v) : "l"(&g_flags[my][tid][0]) : "memory");
        } while (v < target);
      }
      __syncthreads();   // barrier passed for whole CTA

      // issue both stages of h(t+1), split commit groups
      load_a(0, 0); CP_COMMIT;
      load_a(1, 1); CP_COMMIT;
    }
  }

  __syncthreads();
  for (int i = tid; i < 512; i += 256)
    g_c[mBase + (i >> 4)][jhBase + (i & 15)] = s.cst[i >> 4][i & 15];
}

// ---------------- launch ----------------
extern "C" void kernel_launch(void* const* d_in, const int* in_sizes, int n_in,
                              void* d_out, int out_size) {
  const float* x  = (const float*)d_in[0];
  const float* W1 = (const float*)d_in[1];
  const float* U1 = (const float*)d_in[2];
  const float* b1 = (const float*)d_in[3];
  const float* W2 = (const float*)d_in[4];
  const float* U2 = (const float*)d_in[5];
  const float* b2 = (const float*)d_in[6];

  cudaFuncSetAttribute(k_gemm_big, cudaFuncAttributeMaxDynamicSharedMemorySize, (int)sizeof(BigS));
  cudaFuncSetAttribute(k_step,     cudaFuncAttributeMaxDynamicSharedMemorySize, (int)sizeof(StepS));

  k_prep<<<(4 * G4 * 512 + 255) / 256, 256>>>(W1, U1, W2, U2, b1, b2);
  k_conv<<<(M_ * H_ + 255) / 256, 256>>>(x);

  for (int pass = 0; pass < 6; ++pass) {
    int widx = (pass < 5) ? 0 : 2;
    int uidx = widx + 1;
    int lidx = (pass < 5) ? 0 : 1;
    k_gemm_big<<<dim3(G4 / 128, M_ / 128), 256, sizeof(BigS)>>>(widx, lidx);
    k_step<<<dim3(32, 4), 256, sizeof(StepS)>>>(uidx, (pass < 5) ? 1 : 0,
                                                (pass == 5) ? 1 : 0, (float*)d_out);
  }
}

// round 13
// speedup vs baseline: 2.8139x; 1.1068x over previous
#include <cuda_runtime.h>
#include <cuda_fp16.h>
#include <stdint.h>

#define B_ 128
#define T_ 256
#define H_ 512
#define G4 2048          // 4*H, gate-interleaved columns p = 4*jh + gate
#define M_ (B_*T_)       // 32768

// ---------------- device scratch (no allocs allowed) ----------------
__device__ __half g_w16[4][G4][512];      // W1,U1,W2,U2 fp16, transposed [p][k]
__device__ float  g_bias[2][G4];
__device__ __half g_x[M_][H_];            // fp16 input activations (pass-0 GEMM A)
__device__ float  g_Zx[M_][G4];           // x@W + b, gate-interleaved, m = b*T+t
__device__ __half g_hT[64][B_][8];        // h transposed: [jh_group][batch][8 jh]
__device__ float  g_c[B_][H_];
__device__ unsigned g_flags[4][32][32];   // [m-group][cta][pad]: 1 flag per 128B line

// ---------------- helpers ----------------
#define MMA16816(d, a, b) asm volatile( \
  "mma.sync.aligned.m16n8k16.row.col.f32.f16.f16.f32 " \
  "{%0,%1,%2,%3}, {%4,%5,%6,%7}, {%8,%9}, {%0,%1,%2,%3};\n" \
  : "+f"(d[0]), "+f"(d[1]), "+f"(d[2]), "+f"(d[3]) \
  : "r"(a[0]), "r"(a[1]), "r"(a[2]), "r"(a[3]), "r"(b[0]), "r"(b[1]))

__device__ __forceinline__ uint32_t s2u(const void* p) {
  return (uint32_t)__cvta_generic_to_shared(p);
}
__device__ __forceinline__ void ldsm4(uint32_t r[4], uint32_t addr) {
  asm volatile("ldmatrix.sync.aligned.m8n8.x4.shared.b16 {%0,%1,%2,%3}, [%4];\n"
    : "=r"(r[0]), "=r"(r[1]), "=r"(r[2]), "=r"(r[3]) : "r"(addr));
}
__device__ __forceinline__ void cpa16(void* s, const void* g) {
  uint32_t sa = s2u(s);
  asm volatile("cp.async.cg.shared.global [%0], [%1], 16;\n" :: "r"(sa), "l"(g));
}
#define CP_COMMIT asm volatile("cp.async.commit_group;\n")
#define CP_WAIT0  asm volatile("cp.async.wait_group 0;\n")
#define CP_WAIT1  asm volatile("cp.async.wait_group 1;\n")

__device__ __forceinline__ float sigf(float x)     { return 1.f / (1.f + __expf(-x)); }
__device__ __forceinline__ float tanhfast(float x) { return 1.f - 2.f / (1.f + __expf(2.f*x)); }

// ---------------- prep (fused, launch #1) ----------------
__global__ void k_prep(const float* __restrict__ W1, const float* __restrict__ U1,
                       const float* __restrict__ W2, const float* __restrict__ U2,
                       const float* __restrict__ b1, const float* __restrict__ b2) {
  int idx = blockIdx.x * blockDim.x + threadIdx.x;
  if (idx < 4 * G4 * 512) {
    int w   = idx >> 20;
    int rem = idx & ((1 << 20) - 1);
    int p   = rem >> 9;
    int k   = rem & 511;
    int jh = p >> 2, gate = p & 3;
    int j = gate * H_ + jh;
    const float* Mt = (w==0) ? W1 : (w==1) ? U1 : (w==2) ? W2 : U2;
    g_w16[w][p][k] = __float2half(Mt[(size_t)k * G4 + j]);
  }
  if (idx < 2 * G4) {
    int l = idx >> 11;
    int p = idx & (G4 - 1);
    int jh = p >> 2, gate = p & 3;
    const float* b = l ? b2 : b1;
    g_bias[l][p] = b[gate * H_ + jh];
  }
  if (idx < B_ * H_) {
    ((__half*)g_hT)[idx] = __float2half(0.f);
    ((float*)g_c)[idx] = 0.f;
  }
}

// ---------------- conv (launch #2): x fp32 -> fp16 ----------------
__global__ void k_conv(const float* __restrict__ x) {
  int i = blockIdx.x * blockDim.x + threadIdx.x;
  ((__half*)g_x)[i] = __float2half(x[i]);
}

// ---------------- big GEMM (pass 0 only): Zx = x(fp16) @ W1^T + b1 ----------------
struct BigS {
  alignas(16) __half a[2][128][72];
  alignas(16) __half w[2][128][72];
};

__global__ void __launch_bounds__(256, 1) k_gemm_big(int widx, int lidx) {
  extern __shared__ char smraw[];
  BigS& s = *(BigS*)smraw;
  const int tid = threadIdx.x, wid = tid >> 5, lane = tid & 31;
  const int grp = lane >> 2, qid = lane & 3;
  const int mBase = blockIdx.y * 128, nBase = blockIdx.x * 128;
  const int m_off = (wid & 3) * 32, n_off = (wid >> 2) * 64;
  const int aR = lane & 15,                  aC = (lane >> 4) << 3;
  const int bR = ((lane>>4)<<3) + (lane&7),  bC = ((lane >> 3) & 1) << 3;

  float acc[2][8][4];
  #pragma unroll
  for (int mt=0; mt<2; mt++)
    #pragma unroll
    for (int nt=0; nt<8; nt++)
      #pragma unroll
      for (int q=0; q<4; q++) acc[mt][nt][q] = 0.f;

  auto load_blk = [&](int kb, int bufi) {
    int k0 = kb * 64;
    #pragma unroll
    for (int i = tid; i < 1024; i += 256) {
      int r = i >> 3, ch = (i & 7) * 8;
      cpa16(&s.a[bufi][r][ch], &g_x[mBase + r][k0 + ch]);
      cpa16(&s.w[bufi][r][ch], &g_w16[widx][nBase + r][k0 + ch]);
    }
  };

  uint32_t sa[2], sw[2];
  #pragma unroll
  for (int b = 0; b < 2; b++) {
    sa[b] = s2u(&s.a[b][0][0]);
    sw[b] = s2u(&s.w[b][0][0]);
  }

  load_blk(0, 0); CP_COMMIT;
  for (int kb = 0; kb < 8; kb++) {
    CP_WAIT0; __syncthreads();
    if (kb < 7) { load_blk(kb + 1, (kb + 1) & 1); CP_COMMIT; }
    int bf = kb & 1;
    #pragma unroll
    for (int ks = 0; ks < 4; ks++) {
      const int kk = ks * 16;
      uint32_t af[2][4], wf[4][4];
      #pragma unroll
      for (int mt = 0; mt < 2; mt++) {
        uint32_t off = (uint32_t)(((m_off + mt*16 + aR) * 72 + kk + aC) * 2);
        ldsm4(af[mt], sa[bf] + off);
      }
      #pragma unroll
      for (int np = 0; np < 4; np++) {
        uint32_t off = (uint32_t)(((n_off + np*16 + bR) * 72 + kk + bC) * 2);
        ldsm4(wf[np], sw[bf] + off);
      }
      #pragma unroll
      for (int np = 0; np < 4; np++)
        #pragma unroll
        for (int hf = 0; hf < 2; hf++)
          #pragma unroll
          for (int mt = 0; mt < 2; mt++)
            MMA16816(acc[mt][np*2+hf], af[mt], (&wf[np][hf*2]));
    }
    __syncthreads();
  }

  #pragma unroll
  for (int mt = 0; mt < 2; mt++) {
    #pragma unroll
    for (int nt = 0; nt < 8; nt++) {
      int r = mBase + m_off + mt*16 + grp;
      int c = nBase + n_off + nt*8 + qid*2;
      float bx = g_bias[lidx][c], by = g_bias[lidx][c + 1];
      float2 v0 = make_float2(acc[mt][nt][0] + bx, acc[mt][nt][1] + by);
      *(float2*)&g_Zx[r][c] = v0;
      float2 v1 = make_float2(acc[mt][nt][2] + bx, acc[mt][nt][3] + by);
      *(float2*)&g_Zx[r + 8][c] = v1;
    }
  }
}

// ---------------- persistent recurrent pass kernel ----------------
// Tile: m=32 batch rows x n=64 gate cols (16 jh). Grid (32, 4) = 128 CTAs.
// Fused next-pass Zx: after the barrier arrive, each CTA multiplies the h tile
// it already holds (== seq[t-1] == next pass's x[t-1]) by W_next for its own
// 64 columns and streams Zx_next[., t-1] out — hidden in the barrier wait.
struct StepS {
  alignas(16) __half w[64][520];       // U slab (64 p-cols x 512)
  alignas(16) __half wn[64][520];      // W_next slab
  alignas(16) __half a[2][32][264];    // h tile, 2 stages x (32 rows x 256 cols)
  alignas(16) float zs[32][68];
  alignas(16) float cst[32][16];
  alignas(16) float bn[64];            // next-pass bias slice
  unsigned base;
};

__global__ void __launch_bounds__(256, 1) k_step(int uidx, int doW, int wnidx,
                                                 int lnidx, int finalPass,
                                                 float* __restrict__ out) {
  extern __shared__ char smraw[];
  StepS& s = *(StepS*)smraw;
  const int tid = threadIdx.x, wid = tid >> 5, lane = tid & 31;
  const int grp = lane >> 2, qid = lane & 3;
  const int bx = blockIdx.x, my = blockIdx.y;
  const int nBase = bx * 64, mBase = my * 32, jhBase = bx * 16;
  const int m_off = (wid & 1) * 16, n_off = (wid >> 1) * 16;
  const int aR = lane & 15,                  aC = (lane >> 4) << 3;
  const int bR = ((lane>>4)<<3) + (lane&7),  bC = ((lane >> 3) & 1) << 3;

  if (tid == 0) {
    unsigned b;
    asm volatile("ld.acquire.gpu.global.u32 %0, [%1];\n"
                 : "=r"(b) : "l"(&g_flags[my][bx][0]) : "memory");
    s.base = b;
  }
  // U slab: 64 rows x 512
  for (int i = tid; i < 4096; i += 256) {
    int r = i >> 6, ch = (i & 63) * 8;
    *(uint4*)&s.w[r][ch] = *(const uint4*)&g_w16[uidx][nBase + r][ch];
  }
  if (doW) {
    for (int i = tid; i < 4096; i += 256) {
      int r = i >> 6, ch = (i & 63) * 8;
      *(uint4*)&s.wn[r][ch] = *(const uint4*)&g_w16[wnidx][nBase + r][ch];
    }
    if (tid < 64) s.bn[tid] = g_bias[lnidx][nBase + tid];
  }
  for (int i = tid; i < 512; i += 256)
    s.cst[i >> 4][i & 15] = g_c[mBase + (i >> 4)][jhBase + (i & 15)];

  // stage loader: stage st covers jh groups [st*32, st*32+32)
  auto load_a = [&](int st, int bufi) {
    #pragma unroll
    for (int i = tid; i < 1024; i += 256) {
      int r = i >> 5, gg = i & 31;
      cpa16(&s.a[bufi][r][gg * 8], &g_hT[st * 32 + gg][mBase + r][0]);
    }
  };

  load_a(0, 0); CP_COMMIT;
  load_a(1, 1); CP_COMMIT;
  __syncthreads();
  const unsigned base = s.base;

  uint32_t sa[2];
  sa[0] = s2u(&s.a[0][0][0]); sa[1] = s2u(&s.a[1][0][0]);
  const uint32_t swW = s2u(&s.w[0][0]);
  const uint32_t swN = s2u(&s.wn[0][0]);
  const uint32_t aOff = (uint32_t)(((m_off + aR) * 264 + aC) * 2);
  const uint32_t wOff = (uint32_t)(((n_off + bR) * 520 + bC) * 2);

  const int b_l = tid >> 3, jh0 = (tid & 7) * 2;   // 2 cells per thread

  // W_next GEMM over the full resident h tile (both stages valid)
  auto wgemm_store = [&](int tq) {
    float wacc[2][4];
    #pragma unroll
    for (int nt=0; nt<2; nt++)
      #pragma unroll
      for (int q=0; q<4; q++) wacc[nt][q] = 0.f;
    #pragma unroll
    for (int ks = 0; ks < 32; ks++) {
      uint32_t af[4], wf[4];
      ldsm4(af, sa[ks >> 4] + aOff + (ks & 15) * 32);
      ldsm4(wf, swN + wOff + (ks * 16) * 2);
      MMA16816(wacc[0], af, (&wf[0]));
      MMA16816(wacc[1], af, (&wf[2]));
    }
    int r0 = mBase + m_off + grp;
    #pragma unroll
    for (int nt = 0; nt < 2; nt++) {
      int c = n_off + nt*8 + qid*2;
      float bx2 = s.bn[c], by2 = s.bn[c + 1];
      *(float2*)&g_Zx[r0 * T_ + tq][nBase + c] =
          make_float2(wacc[nt][0] + bx2, wacc[nt][1] + by2);
      *(float2*)&g_Zx[(r0 + 8) * T_ + tq][nBase + c] =
          make_float2(wacc[nt][2] + bx2, wacc[nt][3] + by2);
    }
  };

  for (int t = 0; t < T_; t++) {
    // Zx prefetch (this pass)
    const float* zrow = &g_Zx[(mBase + b_l) * T_ + t][nBase + jh0 * 4];
    float4 zx0 = *(const float4*)zrow;
    float4 zx1 = *(const float4*)(zrow + 4);

    float acc[2][4];
    #pragma unroll
    for (int nt=0; nt<2; nt++)
      #pragma unroll
      for (int q=0; q<4; q++) acc[nt][q] = 0.f;

    // U-GEMM, stage 0: K cols 0..255
    CP_WAIT1; __syncthreads();
    #pragma unroll
    for (int ks = 0; ks < 16; ks++) {
      uint32_t af[4], wf[4];
      ldsm4(af, sa[0] + aOff + ks * 32);
      ldsm4(wf, swW + wOff + (ks * 16) * 2);
      MMA16816(acc[0], af, (&wf[0]));
      MMA16816(acc[1], af, (&wf[2]));
    }
    // U-GEMM, stage 1: K cols 256..511
    CP_WAIT0; __syncthreads();
    #pragma unroll
    for (int ks = 0; ks < 16; ks++) {
      uint32_t af[4], wf[4];
      ldsm4(af, sa[1] + aOff + ks * 32);
      ldsm4(wf, swW + wOff + (256 + ks * 16) * 2);
      MMA16816(acc[0], af, (&wf[0]));
      MMA16816(acc[1], af, (&wf[2]));
    }

    // accumulators -> smem
    #pragma unroll
    for (int nt = 0; nt < 2; nt++) {
      int c = n_off + nt*8 + qid*2;
      s.zs[m_off + grp][c]         = acc[nt][0];
      s.zs[m_off + grp][c + 1]     = acc[nt][1];
      s.zs[m_off + 8 + grp][c]     = acc[nt][2];
      s.zs[m_off + 8 + grp][c + 1] = acc[nt][3];
    }
    __syncthreads();     // zs visible; all U-mma reads of s.a done

    // gates + state update: 2 cells per thread
    float hv[2];
    #pragma unroll
    for (int q = 0; q < 2; q++) {
      int jh = jh0 + q;
      float4 z4 = q ? zx1 : zx0;
      float zi = s.zs[b_l][jh*4 + 0] + z4.x;
      float zf = s.zs[b_l][jh*4 + 1] + z4.y;
      float zg = s.zs[b_l][jh*4 + 2] + z4.z;
      float zo = s.zs[b_l][jh*4 + 3] + z4.w;
      float ig = sigf(zi), fg = sigf(zf), gg = tanhfast(zg), og = sigf(zo);
      float c0 = s.cst[b_l][jh];
      float cn = fg * c0 + ig * gg;
      s.cst[b_l][jh] = cn;
      hv[q] = og * tanhfast(cn);
    }
    {
      int bg = mBase + b_l;
      int jhg = jhBase + jh0;
      __half2 ph;
      ph.x = __float2half(hv[0]);
      ph.y = __float2half(hv[1]);
      *(__half2*)&g_hT[jhg >> 3][bg][jhg & 7] = ph;
      if (finalPass && t == T_ - 1) {
        out[bg * H_ + jhg]     = hv[0];
        out[bg * H_ + jhg + 1] = hv[1];
      }
    }

    if (t < T_ - 1) {
      __syncthreads();   // all h stores issued
      unsigned target = base + (unsigned)t + 1;
      if (tid == 0) {
        asm volatile("fence.acq_rel.gpu;\n" ::: "memory");
        asm volatile("st.release.gpu.global.u32 [%0], %1;\n"
                     :: "l"(&g_flags[my][bx][0]), "r"(target) : "memory");
      }
      // hidden work: next-pass Zx for time t-1 (s.a == seq[t-1] still resident)
      if (doW && t > 0) wgemm_store(t - 1);
      if (tid < 32) {
        unsigned v;
        do {
          asm volatile("ld.acquire.gpu.global.u32 %0, [%1];\n"
                       : "=r"(v) : "l"(&g_flags[my][tid][0]) : "memory");
        } while (v < target);
      }
      __syncthreads();   // barrier passed for whole CTA

      load_a(0, 0); CP_COMMIT;
      load_a(1, 1); CP_COMMIT;
    } else if (doW) {
      // t == 255: finish Zx_next[254], then one extra exchange for Zx_next[255]
      __syncthreads();   // all h(255) stores issued
      unsigned target = base + (unsigned)T_;
      if (tid == 0) {
        asm volatile("fence.acq_rel.gpu;\n" ::: "memory");
        asm volatile("st.release.gpu.global.u32 [%0], %1;\n"
                     :: "l"(&g_flags[my][bx][0]), "r"(target) : "memory");
      }
      wgemm_store(254);
      if (tid < 32) {
        unsigned v;
        do {
          asm volatile("ld.acquire.gpu.global.u32 %0, [%1];\n"
                       : "=r"(v) : "l"(&g_flags[my][tid][0]) : "memory");
        } while (v < target);
      }
      __syncthreads();

      load_a(0, 0); CP_COMMIT;
      load_a(1, 1); CP_COMMIT;
      CP_WAIT0; __syncthreads();
      wgemm_store(255);                 // seq[255] @ W_next
    }
  }

  __syncthreads();
  for (int i = tid; i < 512; i += 256)
    g_c[mBase + (i >> 4)][jhBase + (i & 15)] = s.cst[i >> 4][i & 15];
}

// ---------------- launch ----------------
extern "C" void kernel_launch(void* const* d_in, const int* in_sizes, int n_in,
                              void* d_out, int out_size) {
  const float* x  = (const float*)d_in[0];
  const float* W1 = (const float*)d_in[1];
  const float* U1 = (const float*)d_in[2];
  const float* b1 = (const float*)d_in[3];
  const float* W2 = (const float*)d_in[4];
  const float* U2 = (const float*)d_in[5];
  const float* b2 = (const float*)d_in[6];

  cudaFuncSetAttribute(k_gemm_big, cudaFuncAttributeMaxDynamicSharedMemorySize, (int)sizeof(BigS));
  cudaFuncSetAttribute(k_step,     cudaFuncAttributeMaxDynamicSharedMemorySize, (int)sizeof(StepS));

  k_prep<<<(4 * G4 * 512 + 255) / 256, 256>>>(W1, U1, W2, U2, b1, b2);
  k_conv<<<(M_ * H_ + 255) / 256, 256>>>(x);
  // pass 0 input GEMM: Zx = x @ W1 + b1
  k_gemm_big<<<dim3(G4 / 128, M_ / 128), 256, sizeof(BigS)>>>(0, 0);

  for (int pass = 0; pass < 6; ++pass) {
    int uidx  = (pass < 5) ? 1 : 3;            // U1 or U2
    int doW   = (pass < 5) ? 1 : 0;            // produce next pass's Zx?
    int wnidx = (pass <= 3) ? 0 : 2;           // W1 or W2 for next pass
    int lnidx = (pass <= 3) ? 0 : 1;           // bias for next pass
    k_step<<<dim3(32, 4), 256, sizeof(StepS)>>>(uidx, doW, wnidx, lnidx,
                                                (pass == 5) ? 1 : 0, (float*)d_out);
  }
}